// round 2
// baseline (speedup 1.0000x reference)
#include <cuda_runtime.h>
#include <float.h>

#define NB 2048
#define NS 200
#define ND 64
#define NH 4
#define NH1 64
#define NH2 32
#define NF 256
#define KST 209     // transposed keys row stride (odd -> conflict-free)
#define NTHR 416    // 13 warps: thread = (s in [0,208), head-pair)

// Split layer-1 weights (built once per launch; q folded in per-CTA later)
__device__ float g_W1a[NH*ND*NH1];  // Wk + Wd
__device__ float g_W1b[NH*ND*NH1];  // Wkq
__device__ float g_W1c[NH*ND*NH1];  // Wq - Wd

__global__ void prep_kernel(const float* __restrict__ W1) {
    int idx = blockIdx.x * blockDim.x + threadIdx.x;   // NH*ND*NH1 = 16384
    if (idx >= NH*ND*NH1) return;
    int j = idx & 63;
    int i = (idx >> 6) & 63;
    int h = idx >> 12;
    const float* w = W1 + h*NF*NH1;
    float wk  = w[(i      )*NH1 + j];
    float wq  = w[(64 + i )*NH1 + j];
    float wkq = w[(128 + i)*NH1 + j];
    float wd  = w[(192 + i)*NH1 + j];
    g_W1a[idx] = wk + wd;
    g_W1b[idx] = wkq;
    g_W1c[idx] = wq - wd;
}

// ---- packed f32x2 helpers (Blackwell FFMA2: 2 fp32 FMA / instr) ----
__device__ __forceinline__ void ffma2(unsigned long long &d, unsigned long long a, unsigned long long b) {
    asm("fma.rn.f32x2 %0, %1, %2, %0;" : "+l"(d) : "l"(a), "l"(b));
}
__device__ __forceinline__ unsigned long long bcast2(float x) {
    unsigned long long r;
    asm("mov.b64 %0, {%1, %1};" : "=l"(r) : "f"(x));
    return r;
}
__device__ __forceinline__ float2 unpack2(unsigned long long v) {
    float lo, hi;
    asm("mov.b64 {%0, %1}, %2;" : "=f"(lo), "=f"(hi) : "l"(v));
    return make_float2(lo, hi);
}
__device__ __forceinline__ unsigned long long pack2(float x, float y) {
    unsigned long long r;
    asm("mov.b64 %0, {%1, %2};" : "=l"(r) : "f"(x), "f"(y));
    return r;
}

// Shared memory layout (floats); all offsets 16B-aligned.
#define OFF_W1AB 0          // 16384  combined layer-1 weights (q folded)
#define OFF_W2   16384      // 8192
#define OFF_K    24576      // 64*209 = 13376 transposed keys
#define OFF_SC   37952      // 4*208
#define OFF_C1   38784      // 256
#define OFF_Q    39040      // 64
#define OFF_W3   39104      // 128
#define OFF_B2   39232      // 128
#define OFF_OUTH 39360      // 256
#define OFF_MISC 39616      // b3[0..3] a1[4..7] a2[8..11] comb[16..79]
#define SMEM_FLOATS 39712   // 158848 bytes

__global__ __launch_bounds__(NTHR, 1)
void attn_main(const float* __restrict__ query,
               const float* __restrict__ keys,
               const int*   __restrict__ kmask,
               const float* __restrict__ b1,
               const float* __restrict__ a1,
               const float* __restrict__ W2,
               const float* __restrict__ b2,
               const float* __restrict__ a2,
               const float* __restrict__ W3,
               const float* __restrict__ b3,
               const float* __restrict__ Wo,
               const float* __restrict__ bo,
               float* __restrict__ out)
{
    extern __shared__ float sm[];
    float* sW1ab = sm + OFF_W1AB;
    float* sW2   = sm + OFF_W2;
    float* sK    = sm + OFF_K;
    float* sSc   = sm + OFF_SC;
    float* sC1   = sm + OFF_C1;
    float* sQ    = sm + OFF_Q;
    float* sW3   = sm + OFF_W3;
    float* sB2   = sm + OFF_B2;
    float* sOutH = sm + OFF_OUTH;
    float* sMisc = sm + OFF_MISC;

    const int b   = blockIdx.x;
    const int tid = threadIdx.x;

    // ---- Phase A: cooperative loads of small operands + keys ----
    for (int t = tid; t < NH*NH1*NH2; t += NTHR) sW2[t] = W2[t];
    if (tid < NH*NH2) { sW3[tid] = W3[tid]; sB2[tid] = b2[tid]; }
    if (tid < ND) sQ[tid] = query[b*ND + tid];
    if (tid < NH) { sMisc[tid] = b3[tid]; sMisc[4+tid] = a1[tid]; sMisc[8+tid] = a2[tid]; }

    // keys -> transposed smem tile sK[d][s]; zero the padded columns
    if (tid < ND) {
        float* row = sK + tid*KST;
        #pragma unroll
        for (int p = NS; p < KST; p++) row[p] = 0.f;
    }
    const float4* kg = (const float4*)(keys + (size_t)b * (NS*ND));
    for (int t = tid; t < (NS*ND)/4; t += NTHR) {
        float4 v = kg[t];
        int e = t * 4;
        int s = e >> 6;
        int d = e & 63;
        float* dst = sK + d*KST + s;
        dst[0*KST] = v.x; dst[1*KST] = v.y; dst[2*KST] = v.z; dst[3*KST] = v.w;
    }
    __syncthreads();

    // ---- Phase B: fold q into layer-1 weights; compute per-(h,j) bias ----
    // W1ab[i][j] = (Wk+Wd)[i][j] + q_i * Wkq[i][j]
    for (int t = tid; t < NH*ND*NH1; t += NTHR) {
        int i = (t >> 6) & 63;
        sW1ab[t] = fmaf(sQ[i], g_W1b[t], g_W1a[t]);
    }
    // c1 = q @ (Wq - Wd) + b1
    if (tid < NH*NH1) {
        int h = tid >> 6, j = tid & 63;
        const float* wc = g_W1c + h*(ND*NH1) + j;
        float acc = b1[h*NH1 + j];
        #pragma unroll 8
        for (int i = 0; i < ND; i++) acc = fmaf(sQ[i], wc[i*NH1], acc);
        sC1[tid] = acc;
    }
    __syncthreads();

    // ---- Phase C: per (s, head) MLP -> scores ----
    {
        const int s     = tid % 208;
        const int hbase = (tid / 208) * 2;
        const bool valid = (s < NS) && (kmask[b*NS + s] != 0);

        #pragma unroll 1
        for (int rep = 0; rep < 2; rep++) {
            const int h = hbase + rep;

            // layer 1: acc[64] = c1 + k @ W1ab   (packed f32x2)
            unsigned long long acc[32];
            {
                const unsigned long long* c1p = (const unsigned long long*)(sC1 + h*NH1);
                #pragma unroll
                for (int jj = 0; jj < 32; jj++) acc[jj] = c1p[jj];
            }
            const float* wbase = sW1ab + h*(ND*NH1);
            #pragma unroll 4
            for (int i = 0; i < ND; i++) {
                unsigned long long kv2 = bcast2(sK[i*KST + s]);
                const ulonglong2* w = (const ulonglong2*)(wbase + i*NH1);
                #pragma unroll
                for (int jj = 0; jj < 16; jj++) {
                    ulonglong2 ww = w[jj];
                    ffma2(acc[2*jj],   kv2, ww.x);
                    ffma2(acc[2*jj+1], kv2, ww.y);
                }
            }
            // PReLU 1 (pack in place -> h1)
            const float al1 = sMisc[4+h];
            #pragma unroll
            for (int jj = 0; jj < 32; jj++) {
                float2 v = unpack2(acc[jj]);
                v.x = v.x > 0.f ? v.x : al1 * v.x;
                v.y = v.y > 0.f ? v.y : al1 * v.y;
                acc[jj] = pack2(v.x, v.y);
            }
            // layer 2: 64 -> 32
            unsigned long long acc2[16];
            {
                const unsigned long long* bp = (const unsigned long long*)(sB2 + h*NH2);
                #pragma unroll
                for (int jj = 0; jj < 16; jj++) acc2[jj] = bp[jj];
            }
            const float* w2b = sW2 + h*(NH1*NH2);
            #pragma unroll 4
            for (int ii = 0; ii < 32; ii++) {      // two h1 elements per iter
                float2 hv = unpack2(acc[ii]);
                unsigned long long e2 = bcast2(hv.x);
                unsigned long long o2 = bcast2(hv.y);
                const ulonglong2* wr = (const ulonglong2*)(w2b + ii*2*NH2);
                #pragma unroll
                for (int jj = 0; jj < 8; jj++) {   // even row (h1 elem 2*ii)
                    ulonglong2 we = wr[jj];
                    ffma2(acc2[2*jj],   e2, we.x);
                    ffma2(acc2[2*jj+1], e2, we.y);
                }
                #pragma unroll
                for (int jj = 0; jj < 8; jj++) {   // odd row (h1 elem 2*ii+1)
                    ulonglong2 wo = wr[8+jj];
                    ffma2(acc2[2*jj],   o2, wo.x);
                    ffma2(acc2[2*jj+1], o2, wo.y);
                }
            }
            // PReLU 2 + layer-3 dot
            const float al2 = sMisc[8+h];
            float sc = sMisc[h];   // b3[h]
            const float* w3r = sW3 + h*NH2;
            #pragma unroll
            for (int jj = 0; jj < 16; jj++) {
                float2 v = unpack2(acc2[jj]);
                float x0 = v.x > 0.f ? v.x : al2 * v.x;
                float x1 = v.y > 0.f ? v.y : al2 * v.y;
                sc = fmaf(x0, w3r[2*jj], sc);
                sc = fmaf(x1, w3r[2*jj+1], sc);
            }
            sSc[h*208 + s] = valid ? sc : -FLT_MAX;
        }
    }
    __syncthreads();

    // ---- Phase D: masked softmax per head (warp w = head w) ----
    {
        int warp = tid >> 5, lane = tid & 31;
        if (warp < NH) {
            float* row = sSc + warp*208;
            float m = -FLT_MAX;
            for (int t = lane; t < NS; t += 32) m = fmaxf(m, row[t]);
            #pragma unroll
            for (int o = 16; o > 0; o >>= 1) m = fmaxf(m, __shfl_xor_sync(0xffffffffu, m, o));
            float sum = 0.f;
            for (int t = lane; t < NS; t += 32) {
                float v = row[t];
                float e = (v > -1e38f) ? expf(v - m) : 0.f;
                row[t] = e;
                sum += e;
            }
            #pragma unroll
            for (int o = 16; o > 0; o >>= 1) sum += __shfl_xor_sync(0xffffffffu, sum, o);
            float inv = (sum > 0.f) ? (1.f / sum) : 0.f;   // all-masked -> zeros
            for (int t = lane; t < NS; t += 32) row[t] *= inv;
        }
    }
    __syncthreads();

    // ---- Phase E: weighted sum over keys, head mean, output projection ----
    if (tid < NH*ND) {
        int h = tid >> 6, d = tid & 63;
        const float* w    = sSc + h*208;
        const float* kcol = sK + d*KST;
        float acc = 0.f;
        #pragma unroll 8
        for (int t = 0; t < NS; t++) acc = fmaf(w[t], kcol[t], acc);
        sOutH[h*ND + d] = acc;
    }
    __syncthreads();
    if (tid < ND) {
        float c = 0.25f * (sOutH[tid] + sOutH[64+tid] + sOutH[128+tid] + sOutH[192+tid]);
        sMisc[16 + tid] = c;
    }
    __syncthreads();
    if (tid < ND) {
        float acc = bo[tid];
        #pragma unroll 8
        for (int d2 = 0; d2 < ND; d2++) acc = fmaf(sMisc[16 + d2], Wo[d2*ND + tid], acc);
        out[b*ND + tid] = acc;
    }
}

extern "C" void kernel_launch(void* const* d_in, const int* in_sizes, int n_in,
                              void* d_out, int out_size) {
    const float* query = (const float*)d_in[0];
    const float* keys  = (const float*)d_in[1];
    const int*   kmask = (const int*)  d_in[2];
    const float* W1    = (const float*)d_in[3];
    const float* b1    = (const float*)d_in[4];
    const float* a1    = (const float*)d_in[5];
    const float* W2    = (const float*)d_in[6];
    const float* b2    = (const float*)d_in[7];
    const float* a2    = (const float*)d_in[8];
    const float* W3    = (const float*)d_in[9];
    const float* b3    = (const float*)d_in[10];
    const float* Wo    = (const float*)d_in[11];
    const float* bo    = (const float*)d_in[12];
    float* out = (float*)d_out;

    cudaFuncSetAttribute(attn_main, cudaFuncAttributeMaxDynamicSharedMemorySize,
                         SMEM_FLOATS * (int)sizeof(float));

    prep_kernel<<<64, 256>>>(W1);
    attn_main<<<NB, NTHR, SMEM_FLOATS * sizeof(float)>>>(
        query, keys, kmask, b1, a1, W2, b2, a2, W3, b3, Wo, bo, out);
}

// round 4
// speedup vs baseline: 1.8594x; 1.8594x over previous
#include <cuda_runtime.h>
#include <float.h>

#define NB 2048
#define NS 200
#define NSP 208      // padded positions
#define ND 64
#define NH 4
#define NH1 64
#define NH2 32
#define NF 256
#define KST 212      // transposed keys row stride (multiple of 4 -> float4-aligned)
#define H1ST 224     // H1T row stride
#define NTHR 416     // 13 warps

// Split layer-1 weights (built once per launch)
__device__ float g_W1a[NH*ND*NH1];   // Wk + Wd
__device__ float g_W1b[NH*ND*NH1];   // Wkq
__device__ float g_W1c[NH*ND*NH1];   // Wq - Wd
__device__ float g_C1[NB*NH*NH1];    // per-batch layer-1 bias: q@(Wq-Wd)+b1

__global__ void prep_kernel(const float* __restrict__ W1) {
    int idx = blockIdx.x * blockDim.x + threadIdx.x;   // NH*ND*NH1 = 16384
    if (idx >= NH*ND*NH1) return;
    int j = idx & 63;
    int i = (idx >> 6) & 63;
    int h = idx >> 12;
    const float* w = W1 + h*NF*NH1;
    float wk  = w[(i      )*NH1 + j];
    float wq  = w[(64 + i )*NH1 + j];
    float wkq = w[(128 + i)*NH1 + j];
    float wd  = w[(192 + i)*NH1 + j];
    g_W1a[idx] = wk + wd;
    g_W1b[idx] = wkq;
    g_W1c[idx] = wq - wd;
}

// c1[b][h][j] = b1[h][j] + sum_i q[b][i] * W1c[h][i][j], 32 batches per block
__global__ void prep2_kernel(const float* __restrict__ query, const float* __restrict__ b1) {
    __shared__ float sq[32*64];
    int tid = threadIdx.x;
    int b0 = blockIdx.x * 32;
    for (int t = tid; t < 32*64; t += 256) sq[t] = query[b0*64 + t];
    __syncthreads();
    int h = tid >> 6, j = tid & 63;
    float bias = b1[h*64 + j];
    float acc[32];
    #pragma unroll
    for (int bb = 0; bb < 32; bb++) acc[bb] = bias;
    const float* wcol = g_W1c + h*4096 + j;
    #pragma unroll 4
    for (int i = 0; i < 64; i++) {
        float wv = wcol[i*64];
        #pragma unroll
        for (int bb = 0; bb < 32; bb++) acc[bb] = fmaf(sq[bb*64 + i], wv, acc[bb]);
    }
    for (int bb = 0; bb < 32; bb++) g_C1[(b0+bb)*256 + tid] = acc[bb];
}

// ---- packed f32x2 helpers ----
__device__ __forceinline__ void ffma2(unsigned long long &d, unsigned long long a, unsigned long long b) {
    asm("fma.rn.f32x2 %0, %1, %2, %0;" : "+l"(d) : "l"(a), "l"(b));
}
__device__ __forceinline__ unsigned long long bcast2(float x) {
    unsigned long long r;
    asm("mov.b64 %0, {%1, %1};" : "=l"(r) : "f"(x));
    return r;
}
__device__ __forceinline__ float2 unpack2(unsigned long long v) {
    float lo, hi;
    asm("mov.b64 {%0, %1}, %2;" : "=f"(lo), "=f"(hi) : "l"(v));
    return make_float2(lo, hi);
}

// Shared memory layout (floats), all offsets multiples of 4 (16B-aligned).
#define OFF_W1AB 0                       // 16384
#define OFF_W2   16384                   // 8192
#define OFF_K    24576                   // 64*212 = 13568
#define OFF_H1T  38144                   // 64*224 = 14336
#define OFF_SC   52480                   // 4*208 = 832
#define OFF_C1   53312                   // 256
#define OFF_Q    53568                   // 64
#define OFF_W3   53632                   // 128
#define OFF_B2   53760                   // 128
#define OFF_OUTH 53888                   // 256
#define OFF_MASK 54144                   // 208
#define OFF_MISC 54352                   // b3[0..3] a1[4..7] a2[8..11] comb[16..79]
#define SMEM_FLOATS 54448                // 217792 bytes

__global__ __launch_bounds__(NTHR, 1)
void attn_main(const float* __restrict__ query,
               const float* __restrict__ keys,
               const int*   __restrict__ kmask,
               const float* __restrict__ a1,
               const float* __restrict__ W2,
               const float* __restrict__ b2,
               const float* __restrict__ a2,
               const float* __restrict__ W3,
               const float* __restrict__ b3,
               const float* __restrict__ Wo,
               const float* __restrict__ bo,
               float* __restrict__ out)
{
    extern __shared__ float sm[];
    float* sW1ab = sm + OFF_W1AB;
    float* sW2   = sm + OFF_W2;
    float* sK    = sm + OFF_K;
    float* sH1T  = sm + OFF_H1T;
    float* sSc   = sm + OFF_SC;
    float* sC1   = sm + OFF_C1;
    float* sQ    = sm + OFF_Q;
    float* sW3   = sm + OFF_W3;
    float* sB2   = sm + OFF_B2;
    float* sOutH = sm + OFF_OUTH;
    float* sMask = sm + OFF_MASK;
    float* sMisc = sm + OFF_MISC;

    const int b   = blockIdx.x;
    const int tid = threadIdx.x;

    // ---- Phase A: cooperative loads ----
    for (int t = tid; t < NH*NH1*NH2; t += NTHR) sW2[t] = W2[t];
    if (tid < NH*NH2) { sW3[tid] = W3[tid]; sB2[tid] = b2[tid]; }
    if (tid < ND) sQ[tid] = query[b*ND + tid];
    if (tid < NH*NH1) sC1[tid] = g_C1[b*256 + tid];
    if (tid < NH) { sMisc[tid] = b3[tid]; sMisc[4+tid] = a1[tid]; sMisc[8+tid] = a2[tid]; }
    if (tid < NSP) {
        float v = 0.f;
        if (tid < NS) v = (kmask[b*NS + tid] != 0) ? 1.f : 0.f;
        sMask[tid] = v;
    }
    // keys -> transposed smem sK[d][s]; zero pad columns
    if (tid < ND) {
        float* row = sK + tid*KST;
        #pragma unroll
        for (int p = NS; p < KST; p++) row[p] = 0.f;
    }
    const float4* kg = (const float4*)(keys + (size_t)b * (NS*ND));
    for (int t = tid; t < (NS*ND)/4; t += NTHR) {
        float4 v = kg[t];
        int e = t * 4;
        int s = e >> 6;
        int d = e & 63;
        float* dst = sK + d*KST + s;
        dst[0*KST] = v.x; dst[1*KST] = v.y; dst[2*KST] = v.z; dst[3*KST] = v.w;
    }
    __syncthreads();

    // ---- Phase B: fold q into layer-1 weights, stored PERMUTED per row:
    //   logical col n -> pos ((n>>2)&1)*32 + (n>>3)*4 + (n&3)
    // so lane tn reads its two 16B blocks at word offsets tn*4 and 32+tn*4
    // (8 distinct bank-groups per 8-lane phase group -> conflict-free).
    for (int t = tid; t < NH*ND*NH1; t += NTHR) {
        int n = t & 63;
        int i = (t >> 6) & 63;
        int h = t >> 12;
        int pn = ((n >> 2) & 1)*32 + (n >> 3)*4 + (n & 3);
        sW1ab[h*4096 + i*64 + pn] = fmaf(sQ[i], g_W1b[t], g_W1a[t]);
    }
    __syncthreads();

    // ---- Phase C: per-head GEMM1 (208x64x64) -> PReLU -> GEMM2 (208x32x64) -> scores ----
    const int tm  = tid >> 3;        // 0..51  (M tile of 4 positions)
    const int tn  = tid & 7;         // 0..7
    const int s0  = tm * 4;
    const int n8  = tn * 8;          // GEMM1 logical N offset
    const int n4  = tn * 4;          // GEMM2 N offset

    #pragma unroll 1
    for (int h = 0; h < NH; h++) {
        const float al1 = sMisc[4+h];
        const float al2 = sMisc[8+h];

        // --- GEMM1: acc[m][j] over 4 s x 8 n (packed pairs) ---
        unsigned long long acc[4][4];
        {
            const ulonglong2* c1p = (const ulonglong2*)(sC1 + h*NH1 + n8);
            ulonglong2 c0 = c1p[0], c1v = c1p[1];
            #pragma unroll
            for (int m = 0; m < 4; m++) {
                acc[m][0] = c0.x; acc[m][1] = c0.y; acc[m][2] = c1v.x; acc[m][3] = c1v.y;
            }
        }
        {
            const float* wb = sW1ab + h*(ND*NH1);
            const float* kb = sK + s0;
            #pragma unroll 8
            for (int k = 0; k < ND; k++) {
                float4 kv = *(const float4*)(kb + k*KST);
                ulonglong2 w01 = *(const ulonglong2*)(wb + k*NH1 + n4);        // cols n8..n8+3
                ulonglong2 w23 = *(const ulonglong2*)(wb + k*NH1 + 32 + n4);   // cols n8+4..n8+7
                unsigned long long k0 = bcast2(kv.x), k1 = bcast2(kv.y),
                                   k2 = bcast2(kv.z), k3 = bcast2(kv.w);
                ffma2(acc[0][0], k0, w01.x); ffma2(acc[0][1], k0, w01.y);
                ffma2(acc[0][2], k0, w23.x); ffma2(acc[0][3], k0, w23.y);
                ffma2(acc[1][0], k1, w01.x); ffma2(acc[1][1], k1, w01.y);
                ffma2(acc[1][2], k1, w23.x); ffma2(acc[1][3], k1, w23.y);
                ffma2(acc[2][0], k2, w01.x); ffma2(acc[2][1], k2, w01.y);
                ffma2(acc[2][2], k2, w23.x); ffma2(acc[2][3], k2, w23.y);
                ffma2(acc[3][0], k3, w01.x); ffma2(acc[3][1], k3, w01.y);
                ffma2(acc[3][2], k3, w23.x); ffma2(acc[3][3], k3, w23.y);
            }
        }
        // PReLU1 + store transposed H1T[n][s] with XOR swizzle (key = tn)
        {
            const int col = s0 ^ (tn*4);
            #pragma unroll
            for (int j = 0; j < 4; j++) {
                float2 v0 = unpack2(acc[0][j]);
                float2 v1 = unpack2(acc[1][j]);
                float2 v2 = unpack2(acc[2][j]);
                float2 v3 = unpack2(acc[3][j]);
                float4 e, o;
                e.x = v0.x > 0.f ? v0.x : al1*v0.x;
                e.y = v1.x > 0.f ? v1.x : al1*v1.x;
                e.z = v2.x > 0.f ? v2.x : al1*v2.x;
                e.w = v3.x > 0.f ? v3.x : al1*v3.x;
                o.x = v0.y > 0.f ? v0.y : al1*v0.y;
                o.y = v1.y > 0.f ? v1.y : al1*v1.y;
                o.z = v2.y > 0.f ? v2.y : al1*v2.y;
                o.w = v3.y > 0.f ? v3.y : al1*v3.y;
                *(float4*)(sH1T + (n8 + 2*j    )*H1ST + col) = e;
                *(float4*)(sH1T + (n8 + 2*j + 1)*H1ST + col) = o;
            }
        }
        __syncthreads();

        // --- GEMM2: acc2[m][j] over 4 s x 4 n (packed pairs) ---
        unsigned long long acc2[4][2];
        {
            ulonglong2 bb = *(const ulonglong2*)(sB2 + h*NH2 + n4);
            #pragma unroll
            for (int m = 0; m < 4; m++) { acc2[m][0] = bb.x; acc2[m][1] = bb.y; }
        }
        {
            const float* w2b = sW2 + h*(NH1*NH2) + n4;
            #pragma unroll 8
            for (int k = 0; k < NH1; k++) {
                const int col = s0 ^ ((k >> 3) * 4);
                float4 hv = *(const float4*)(sH1T + k*H1ST + col);
                ulonglong2 wv = *(const ulonglong2*)(w2b + k*NH2);
                unsigned long long h0 = bcast2(hv.x), h1 = bcast2(hv.y),
                                   h2 = bcast2(hv.z), h3 = bcast2(hv.w);
                ffma2(acc2[0][0], h0, wv.x); ffma2(acc2[0][1], h0, wv.y);
                ffma2(acc2[1][0], h1, wv.x); ffma2(acc2[1][1], h1, wv.y);
                ffma2(acc2[2][0], h2, wv.x); ffma2(acc2[2][1], h2, wv.y);
                ffma2(acc2[3][0], h3, wv.x); ffma2(acc2[3][1], h3, wv.y);
            }
        }
        // PReLU2 + layer-3 partial dot + 8-lane reduction -> scores
        {
            float4 w3v = *(const float4*)(sW3 + h*NH2 + n4);
            float part[4];
            #pragma unroll
            for (int m = 0; m < 4; m++) {
                float2 v0 = unpack2(acc2[m][0]);
                float2 v1 = unpack2(acc2[m][1]);
                float x0 = v0.x > 0.f ? v0.x : al2*v0.x;
                float x1 = v0.y > 0.f ? v0.y : al2*v0.y;
                float x2 = v1.x > 0.f ? v1.x : al2*v1.x;
                float x3 = v1.y > 0.f ? v1.y : al2*v1.y;
                part[m] = x0*w3v.x + x1*w3v.y + x2*w3v.z + x3*w3v.w;
            }
            #pragma unroll
            for (int off = 1; off < 8; off <<= 1) {
                #pragma unroll
                for (int m = 0; m < 4; m++)
                    part[m] += __shfl_xor_sync(0xffffffffu, part[m], off);
            }
            if (tn == 0) {
                float b3h = sMisc[h];
                #pragma unroll
                for (int m = 0; m < 4; m++) {
                    int s = s0 + m;
                    sSc[h*NSP + s] = (sMask[s] != 0.f) ? (part[m] + b3h) : -FLT_MAX;
                }
            }
        }
        __syncthreads();
    }

    // ---- Phase D: masked softmax per head (warp w = head w) ----
    {
        int warp = tid >> 5, lane = tid & 31;
        if (warp < NH) {
            float* row = sSc + warp*NSP;
            float m = -FLT_MAX;
            for (int t = lane; t < NS; t += 32) m = fmaxf(m, row[t]);
            #pragma unroll
            for (int o = 16; o > 0; o >>= 1) m = fmaxf(m, __shfl_xor_sync(0xffffffffu, m, o));
            float sum = 0.f;
            for (int t = lane; t < NS; t += 32) {
                float v = row[t];
                float e = (v > -1e38f) ? expf(v - m) : 0.f;
                row[t] = e;
                sum += e;
            }
            #pragma unroll
            for (int o = 16; o > 0; o >>= 1) sum += __shfl_xor_sync(0xffffffffu, sum, o);
            float inv = (sum > 0.f) ? (1.f / sum) : 0.f;
            for (int t = lane; t < NS; t += 32) row[t] *= inv;
        }
    }
    __syncthreads();

    // ---- Phase E: weighted sum over keys, head mean, output projection ----
    if (tid < NH*ND) {
        int h = tid >> 6, d = tid & 63;
        const float* w    = sSc + h*NSP;
        const float* kcol = sK + d*KST;
        float a0 = 0.f, a1_ = 0.f, a2_ = 0.f, a3_ = 0.f;
        #pragma unroll 4
        for (int t = 0; t < NS; t += 4) {
            a0  = fmaf(w[t  ], kcol[t  ], a0);
            a1_ = fmaf(w[t+1], kcol[t+1], a1_);
            a2_ = fmaf(w[t+2], kcol[t+2], a2_);
            a3_ = fmaf(w[t+3], kcol[t+3], a3_);
        }
        sOutH[h*ND + d] = (a0 + a1_) + (a2_ + a3_);
    }
    __syncthreads();
    if (tid < ND) {
        float c = 0.25f * (sOutH[tid] + sOutH[64+tid] + sOutH[128+tid] + sOutH[192+tid]);
        sMisc[16 + tid] = c;
    }
    __syncthreads();
    if (tid < ND) {
        float e0 = bo[tid], e1 = 0.f;
        #pragma unroll 4
        for (int d2 = 0; d2 < ND; d2 += 2) {
            e0 = fmaf(sMisc[16 + d2],     Wo[(d2  )*ND + tid], e0);
            e1 = fmaf(sMisc[16 + d2 + 1], Wo[(d2+1)*ND + tid], e1);
        }
        out[b*ND + tid] = e0 + e1;
    }
}

extern "C" void kernel_launch(void* const* d_in, const int* in_sizes, int n_in,
                              void* d_out, int out_size) {
    const float* query = (const float*)d_in[0];
    const float* keys  = (const float*)d_in[1];
    const int*   kmask = (const int*)  d_in[2];
    const float* W1    = (const float*)d_in[3];
    const float* b1    = (const float*)d_in[4];
    const float* a1    = (const float*)d_in[5];
    const float* W2    = (const float*)d_in[6];
    const float* b2    = (const float*)d_in[7];
    const float* a2    = (const float*)d_in[8];
    const float* W3    = (const float*)d_in[9];
    const float* b3    = (const float*)d_in[10];
    const float* Wo    = (const float*)d_in[11];
    const float* bo    = (const float*)d_in[12];
    float* out = (float*)d_out;

    cudaFuncSetAttribute(attn_main, cudaFuncAttributeMaxDynamicSharedMemorySize,
                         SMEM_FLOATS * (int)sizeof(float));

    prep_kernel<<<64, 256>>>(W1);
    prep2_kernel<<<64, 256>>>(query, b1);
    attn_main<<<NB, NTHR, SMEM_FLOATS * sizeof(float)>>>(
        query, keys, kmask, a1, W2, b2, a2, W3, b3, Wo, bo, out);
}